// round 7
// baseline (speedup 1.0000x reference)
#include <cuda_runtime.h>

#define D 128
#define S_SAMP 512
#define MAX_N 100000
#define MAX_A 4096
#define QS_B 33.0f   // sample int4 scale (clip at ~2.58 sigma, MSE-optimal)

// Sample cache: nibble-quantized normalized features, 100000 x 128 x 4b = 6.4 MB.
// Row = 4 x uint4; word g holds elements 8g..8g+7, nibble j = elem 8g+j,
// stored biased: clamp(rint(33*v),-8,7)+8.
__device__ uint4 g_xq4[(size_t)MAX_N * 4];
// Anchor cache: int8 @ scale 127, deinterleaved to match nibble lo/hi expansion.
// Row = 32 words; word 2i = elems 8i+{0,2,4,6}, word 2i+1 = 8i+{1,3,5,7}.
__device__ unsigned g_qa8[(size_t)MAX_A * 32];
__device__ unsigned char g_ya[MAX_A];
// Dense prefetched labels: g_ylab[a*S + i] = y[sampled[a*S + i]].
__device__ unsigned char g_ylab[(size_t)MAX_A * S_SAMP];
__device__ float g_per_anchor[MAX_A];

__device__ __forceinline__ int dp4a_su(int a, unsigned b, int c) {
    int r;
    asm("dp4a.s32.u32 %0, %1, %2, %3;" : "=r"(r) : "r"(a), "r"(b), "r"(c));
    return r;
}

// Fused prep: [0,nF) sample quant | [nF,nF+nAb) anchor quant | rest label gather.
__global__ __launch_bounds__(256) void prep_fused(
    const float* __restrict__ x, const int* __restrict__ y,
    const int* __restrict__ anchors, const int* __restrict__ sampled,
    int n, int A, int nF, int nAb) {
    const int b = blockIdx.x;
    const int tid = threadIdx.x;
    const int lane = tid & 31;

    if (b < nF) {
        // ---- Sample-side int4 quant: one warp per 8 rows, MLP=8. ----
        const int warp = (b * 256 + tid) >> 5;
        const int row0 = warp * 8;
        if (row0 >= n) return;
        const int nr = n - row0;
        const float4* x4 = reinterpret_cast<const float4*>(x);
        float4 v[8];
#pragma unroll
        for (int j = 0; j < 8; j++) {
            const int rj = (j < nr) ? (row0 + j) : row0;
            v[j] = __ldg(&x4[(size_t)rj * 32 + lane]);
        }
        unsigned* xq_w = reinterpret_cast<unsigned*>(g_xq4);
#pragma unroll
        for (int j = 0; j < 8; j++) {
            float s = v[j].x * v[j].x + v[j].y * v[j].y + v[j].z * v[j].z + v[j].w * v[j].w;
            s += __shfl_xor_sync(0xffffffffu, s, 16);
            s += __shfl_xor_sync(0xffffffffu, s, 8);
            s += __shfl_xor_sync(0xffffffffu, s, 4);
            s += __shfl_xor_sync(0xffffffffu, s, 2);
            s += __shfl_xor_sync(0xffffffffu, s, 1);
            const float rn = rsqrtf(s) * QS_B;
            int q0 = max(-8, min(7, __float2int_rn(v[j].x * rn)));
            int q1 = max(-8, min(7, __float2int_rn(v[j].y * rn)));
            int q2 = max(-8, min(7, __float2int_rn(v[j].z * rn)));
            int q3 = max(-8, min(7, __float2int_rn(v[j].w * rn)));
            unsigned u16v = (unsigned)(q0 + 8) | ((unsigned)(q1 + 8) << 4) |
                            ((unsigned)(q2 + 8) << 8) | ((unsigned)(q3 + 8) << 12);
            const unsigned other = __shfl_down_sync(0xffffffffu, u16v, 1);
            if (j < nr && (lane & 1) == 0)
                xq_w[(size_t)(row0 + j) * 16 + (lane >> 1)] = u16v | (other << 16);
        }
    } else if (b < nF + nAb) {
        // ---- Anchor-side int8 quant (deinterleaved lo/hi layout). ----
        const int warp = ((b - nF) * 256 + tid) >> 5;
        const int arow0 = warp * 8;
        if (arow0 >= A) return;
        const int nr = A - arow0;
        const float4* x4 = reinterpret_cast<const float4*>(x);
        int ia[8];
        float4 v[8];
#pragma unroll
        for (int j = 0; j < 8; j++)
            ia[j] = __ldg(&anchors[(j < nr) ? (arow0 + j) : arow0]);
#pragma unroll
        for (int j = 0; j < 8; j++)
            v[j] = __ldg(&x4[(size_t)ia[j] * 32 + lane]);
#pragma unroll
        for (int j = 0; j < 8; j++) {
            float s = v[j].x * v[j].x + v[j].y * v[j].y + v[j].z * v[j].z + v[j].w * v[j].w;
            s += __shfl_xor_sync(0xffffffffu, s, 16);
            s += __shfl_xor_sync(0xffffffffu, s, 8);
            s += __shfl_xor_sync(0xffffffffu, s, 4);
            s += __shfl_xor_sync(0xffffffffu, s, 2);
            s += __shfl_xor_sync(0xffffffffu, s, 1);
            const float rn = rsqrtf(s) * 127.0f;
            const int q0 = max(-127, min(127, __float2int_rn(v[j].x * rn)));
            const int q1 = max(-127, min(127, __float2int_rn(v[j].y * rn)));
            const int q2 = max(-127, min(127, __float2int_rn(v[j].z * rn)));
            const int q3 = max(-127, min(127, __float2int_rn(v[j].w * rn)));
            // even lane: bytes 0,1 of (lo,hi) words; odd lane: bytes 2,3.
            unsigned wlo, whi;
            if ((lane & 1) == 0) {
                wlo = (q0 & 0xFF) | ((q2 & 0xFF) << 8);
                whi = (q1 & 0xFF) | ((q3 & 0xFF) << 8);
            } else {
                wlo = ((q0 & 0xFF) << 16) | ((unsigned)(q2 & 0xFF) << 24);
                whi = ((q1 & 0xFF) << 16) | ((unsigned)(q3 & 0xFF) << 24);
            }
            const unsigned olo = __shfl_down_sync(0xffffffffu, wlo, 1);
            const unsigned ohi = __shfl_down_sync(0xffffffffu, whi, 1);
            if (j < nr && (lane & 1) == 0) {
                const int arow = arow0 + j;
                uint2 w2;
                w2.x = wlo | olo;
                w2.y = whi | ohi;
                reinterpret_cast<uint2*>(g_qa8)[(size_t)arow * 16 + (lane >> 1)] = w2;
            }
            if (j < nr && lane == 0) g_ya[arow0 + j] = (unsigned char)__ldg(&y[ia[j]]);
        }
    } else {
        // ---- Label gather: g_ylab[t] = y[sampled[t]], 4 per thread. ----
        const long long t0 = ((long long)(b - nF - nAb) * 256 + tid) * 4;
        const long long total = (long long)A * S_SAMP;
        int sidx[4];
#pragma unroll
        for (int j = 0; j < 4; j++) {
            const long long t = t0 + j;
            sidx[j] = (t < total) ? __ldg(&sampled[t]) : 0;
        }
#pragma unroll
        for (int j = 0; j < 4; j++) {
            const long long t = t0 + j;
            if (t < total) g_ylab[t] = (unsigned char)__ldg(&y[sidx[j]]);
        }
    }
}

// Anchor kernel: int8 anchor x int4 sample via mixed dp4a; labels coalesced.
__global__ __launch_bounds__(256) void anchor_kernel(const int* __restrict__ sampled) {
    const int a = blockIdx.x;
    const int tid = threadIdx.x;
    const int warp = tid >> 5;
    const int lane = tid & 31;
    const int r = lane & 3;   // lane within 4-lane group
    const int g = lane >> 2;  // group 0..7 -> sample slot in pass

    const int ya = g_ya[a];

    // Anchor slice: 8 int8-packed words (lo/hi x 4), covering elems 32r..32r+31.
    int aw[8];
    int sumA = 0;
    {
        const uint4* qa = reinterpret_cast<const uint4*>(g_qa8 + (size_t)a * 32);
        const uint4 p0 = __ldg(&qa[r * 2 + 0]);
        const uint4 p1 = __ldg(&qa[r * 2 + 1]);
        aw[0] = p0.x; aw[1] = p0.y; aw[2] = p0.z; aw[3] = p0.w;
        aw[4] = p1.x; aw[5] = p1.y; aw[6] = p1.z; aw[7] = p1.w;
#pragma unroll
        for (int k = 0; k < 8; k++) sumA = dp4a_su(aw[k], 0x01010101u, sumA);
        sumA += __shfl_xor_sync(0xffffffffu, sumA, 1);
        sumA += __shfl_xor_sync(0xffffffffu, sumA, 2);
    }
    const float kscale = 10.0f / (127.0f * QS_B);
    const float bias8 = 8.0f * (float)sumA;

    float num = 0.0f, den = 0.0f, cntf = 0.0f;
    const int* srow = sampled + (size_t)a * S_SAMP + warp * 64;
    const unsigned char* lrow = g_ylab + (size_t)a * S_SAMP + warp * 64;

#pragma unroll
    for (int half = 0; half < 2; half++) {
        const int idx_l = __ldg(&srow[half * 32 + lane]);
        const int y_l = lrow[half * 32 + lane];  // coalesced: 1 sector per 32
#pragma unroll
        for (int p8 = 0; p8 < 4; p8++) {
            const int sl = p8 * 8 + g;
            const int idx = __shfl_sync(0xffffffffu, idx_l, sl);
            const uint4 q = __ldg(&g_xq4[(size_t)idx * 4 + r]);
            const unsigned w[4] = {q.x, q.y, q.z, q.w};
            int acc = 0;
#pragma unroll
            for (int i = 0; i < 4; i++) {
                acc = dp4a_su(aw[2 * i], w[i] & 0x0F0F0F0Fu, acc);
                acc = dp4a_su(aw[2 * i + 1], (w[i] >> 4) & 0x0F0F0F0Fu, acc);
            }
            acc += __shfl_xor_sync(0xffffffffu, acc, 1);
            acc += __shfl_xor_sync(0xffffffffu, acc, 2);
            const int y_s = __shfl_sync(0xffffffffu, y_l, sl);
            if (r == 0) {
                const float z = ((float)acc - bias8) * kscale;
                const float e = __expf(z);
                den += e;
                if (y_s == ya) { num += e; cntf += 1.0f; }
            }
        }
    }

    num += __shfl_xor_sync(0xffffffffu, num, 4);
    num += __shfl_xor_sync(0xffffffffu, num, 8);
    num += __shfl_xor_sync(0xffffffffu, num, 16);
    den += __shfl_xor_sync(0xffffffffu, den, 4);
    den += __shfl_xor_sync(0xffffffffu, den, 8);
    den += __shfl_xor_sync(0xffffffffu, den, 16);
    cntf += __shfl_xor_sync(0xffffffffu, cntf, 4);
    cntf += __shfl_xor_sync(0xffffffffu, cntf, 8);
    cntf += __shfl_xor_sync(0xffffffffu, cntf, 16);

    __shared__ float s_num[8], s_den[8], s_cnt[8];
    if (lane == 0) { s_num[warp] = num; s_den[warp] = den; s_cnt[warp] = cntf; }
    __syncthreads();
    if (tid == 0) {
        float tn = 0.0f, td = 0.0f, tc = 0.0f;
#pragma unroll
        for (int w = 0; w < 8; w++) { tn += s_num[w]; td += s_den[w]; tc += s_cnt[w]; }
        float per = 0.0f;
        if (tc > 0.0f) per = -logf(tn / td) / tc;
        g_per_anchor[a] = per;
    }
}

// Deterministic tree reduction of per-anchor losses.
__global__ void reduce_kernel(float* __restrict__ out, int A) {
    __shared__ float s[512];
    const int tid = threadIdx.x;
    float v = 0.0f;
    for (int i = tid; i < A; i += 512) v += g_per_anchor[i];
    s[tid] = v;
    __syncthreads();
    for (int o = 256; o > 0; o >>= 1) {
        if (tid < o) s[tid] += s[tid + o];
        __syncthreads();
    }
    if (tid == 0) out[0] = s[0];
}

extern "C" void kernel_launch(void* const* d_in, const int* in_sizes, int n_in,
                              void* d_out, int out_size) {
    const float* x = (const float*)d_in[0];
    const int* y = (const int*)d_in[1];
    const int* anchors = (const int*)d_in[2];
    const int* sampled = (const int*)d_in[3];
    const int n = in_sizes[1];  // N rows
    const int A = in_sizes[2];  // anchors

    const int nF = (n + 63) / 64;                        // sample quant blocks
    const int nAb = (A + 63) / 64;                       // anchor quant blocks
    const int nL = (int)(((long long)A * S_SAMP + 1023) / 1024);  // label gather
    prep_fused<<<nF + nAb + nL, 256>>>(x, y, anchors, sampled, n, A, nF, nAb);
    anchor_kernel<<<A, 256>>>(sampled);
    reduce_kernel<<<1, 512>>>((float*)d_out, A);
}